// round 9
// baseline (speedup 1.0000x reference)
#include <cuda_runtime.h>
#include <cuda_bf16.h>
#include <cstdint>

#define BATCH    128
#define WTOT     8192
#define DDIM     64
#define SSPLIT   8
#define WSEG     (WTOT / SSPLIT)     // 1024
#define WC       64                  // w per staged tile
#define NTILES   (WSEG / WC)         // 16
#define NTHREADS 256
#define KSTEPS   4                   // 64 w / k16 per mma

// dynamic smem layout
#define SM_RAW    0                  // 2 x 16384 fp32 raw tiles
#define SM_TILE   32768              // 2 x 8192 bf16 mma tiles
#define DYN_SMEM  49152

// Scratch partials (no allocations allowed)
__device__ float g_part[BATCH][SSPLIT][DDIM * DDIM];   // upper 16x16 blocks only
__device__ float s_part[BATCH][SSPLIT][DDIM];
__device__ unsigned int done_cnt[BATCH];               // zero-init; reset by finalizer

__device__ __forceinline__ uint32_t smem_u32(const void* p) {
    uint32_t a;
    asm("{ .reg .u64 t; cvta.to.shared.u64 t, %1; cvt.u32.u64 %0, t; }" : "=r"(a) : "l"(p));
    return a;
}
__device__ __forceinline__ uint32_t cvt2(float hi, float lo) {
    uint32_t r; asm("cvt.rn.bf16x2.f32 %0, %1, %2;" : "=r"(r) : "f"(hi), "f"(lo)); return r;
}
__device__ __forceinline__ void sts64(uint32_t addr, uint32_t r0, uint32_t r1) {
    asm volatile("st.shared.v2.b32 [%0], {%1, %2};" :: "r"(addr), "r"(r0), "r"(r1) : "memory");
}
__device__ __forceinline__ void cp16(uint32_t saddr, const void* gaddr) {
    asm volatile("cp.async.cg.shared.global [%0], [%1], 16;" :: "r"(saddr), "l"(gaddr) : "memory");
}
#define CP_COMMIT()  asm volatile("cp.async.commit_group;" ::: "memory")
#define CP_WAIT(n)   asm volatile("cp.async.wait_group %0;" :: "n"(n) : "memory")
__device__ __forceinline__ void ldsm4t(uint32_t& r0, uint32_t& r1, uint32_t& r2, uint32_t& r3,
                                       uint32_t addr) {
    asm volatile("ldmatrix.sync.aligned.m8n8.x4.trans.shared.b16 {%0,%1,%2,%3}, [%4];"
                 : "=r"(r0), "=r"(r1), "=r"(r2), "=r"(r3) : "r"(addr));
}
__device__ __forceinline__ void mma16816(float* d,
                                         uint32_t a0, uint32_t a1, uint32_t a2, uint32_t a3,
                                         uint32_t b0, uint32_t b1) {
    asm volatile(
        "mma.sync.aligned.m16n8k16.row.col.f32.bf16.bf16.f32 "
        "{%0,%1,%2,%3}, {%4,%5,%6,%7}, {%8,%9}, {%0,%1,%2,%3};"
        : "+f"(d[0]), "+f"(d[1]), "+f"(d[2]), "+f"(d[3])
        : "r"(a0), "r"(a1), "r"(a2), "r"(a3), "r"(b0), "r"(b1));
}

// bf16 mma tile: [w][d], 128 B per row, XOR-swizzled by ((w&7)<<4).
#define SWZ(w, d2bytes) ((uint32_t)((w) * 128 + (d2bytes)) ^ (((uint32_t)(w) & 7u) << 4))

__global__ __launch_bounds__(NTHREADS, 4)
void gram_kernel(const float* __restrict__ x, float* __restrict__ out) {
    extern __shared__ __align__(16) uint8_t dynsmem[];
    __shared__ float4 sums[256];                    // 4 KB
    __shared__ unsigned int lastflag;

    const int tid  = threadIdx.x;
    const int wid  = tid >> 5;
    const int lane = tid & 31;
    const int s = blockIdx.x;
    const int b = blockIdx.y;

    const uint32_t raw_s = smem_u32(dynsmem);
    const uint32_t til_s = raw_s + SM_TILE;

    // Phase A role: chunk f = tid + 256*i -> w = f>>4, d-quad d0 = 4*(tid&15)
    const int d0 = 4 * (tid & 15);
    const int w0 = tid >> 4;

    // ---- warp -> upper-triangular 16x16 block(s) ----
    int rA, cAb;
    if (wid < 4)      { rA = wid;     cAb = wid;     }
    else if (wid < 7) { rA = 0;       cAb = wid - 3; }
    else              { rA = 1;       cAb = 2;       }
    const bool dual = (wid < 2);
    const int rB = wid + 1, cBb = 3;   // extra blocks (1,3), (2,3)

    const int kA = (lane & 7) + ((lane & 16) >> 1);
    const int kB = (lane & 7) + (lane & 8);
    const uint32_t swx = ((uint32_t)lane & 7u) << 4;
    const int laneA = lane & 8;
    const int laneB = (lane & 16) >> 1;
    const uint32_t oA1 = (uint32_t)(kA * 128 + (16 * rA + laneA) * 2) ^ swx;
    const uint32_t oB1 = (uint32_t)(kB * 128 + (16 * cAb + laneB) * 2) ^ swx;
    const uint32_t oA2 = (uint32_t)(kA * 128 + (16 * rB + laneA) * 2) ^ swx;
    const uint32_t oB2 = (uint32_t)(kB * 128 + (16 * cBb + laneB) * 2) ^ swx;

    const float4* xb4 = (const float4*)(x + ((long)b * WTOT + (long)s * WSEG) * DDIM);

    float acc1[2][4], acc2[2][4];
#pragma unroll
    for (int t = 0; t < 2; t++)
#pragma unroll
        for (int r = 0; r < 4; r++) { acc1[t][r] = 0.f; acc2[t][r] = 0.f; }

    float sum0 = 0.f, sum1 = 0.f, sum2 = 0.f, sum3 = 0.f;

    // prologue: stage tile 0
#pragma unroll
    for (int i = 0; i < 4; i++) {
        const int f = tid + 256 * i;
        cp16(raw_s + (uint32_t)(f * 16), xb4 + f);
    }
    CP_COMMIT();

#pragma unroll 1
    for (int c = 0; c < NTILES; c++) {
        const int buf = c & 1;

        if (c + 1 < NTILES) {
            const uint32_t rb = raw_s + (uint32_t)((buf ^ 1) * 16384);
            const float4* gsrc = xb4 + (c + 1) * 1024;
#pragma unroll
            for (int i = 0; i < 4; i++) {
                const int f = tid + 256 * i;
                cp16(rb + (uint32_t)(f * 16), gsrc + f);
            }
            CP_COMMIT();
            CP_WAIT(1);     // tile c resident (this thread's chunks)
        } else {
            CP_WAIT(0);
        }

        // ---- Phase A: fp32 raw (thread-private chunks) -> cvt -> bf16 tile ----
        const float4* rp = (const float4*)(dynsmem + buf * 16384);
        const uint32_t tb = til_s + (uint32_t)(buf * 8192);
#pragma unroll
        for (int i = 0; i < 4; i++) {
            float4 v = rp[tid + 256 * i];
            uint32_t r0 = cvt2(v.y, v.x);
            uint32_t r1 = cvt2(v.w, v.z);
            sum0 += v.x; sum1 += v.y; sum2 += v.z; sum3 += v.w;
            const int w = w0 + 16 * i;
            sts64(tb + SWZ(w, d0 * 2), r0, r1);
        }
        __syncthreads();

        // ---- MMA: upper-tri blocks only ----
#pragma unroll
        for (int ks = 0; ks < KSTEPS; ks++) {
            const uint32_t kb = tb + (uint32_t)(ks * 2048);
            uint32_t a0, a1, a2, a3, b0, b1, b2, b3;
            ldsm4t(a0, a1, a2, a3, kb + oA1);
            ldsm4t(b0, b1, b2, b3, kb + oB1);
            mma16816(acc1[0], a0, a1, a2, a3, b0, b1);
            mma16816(acc1[1], a0, a1, a2, a3, b2, b3);
            if (dual) {
                ldsm4t(a0, a1, a2, a3, kb + oA2);
                ldsm4t(b0, b1, b2, b3, kb + oB2);
                mma16816(acc2[0], a0, a1, a2, a3, b0, b1);
                mma16816(acc2[1], a0, a1, a2, a3, b2, b3);
            }
        }
        // MMA(c) is ordered before phaseA(c+2) overwrite by sync(c+1).
    }

    // ---- write Gram partial blocks (upper triangle only) ----
    {
        const int g = lane >> 2;
        const int col2 = 2 * (lane & 3);
        float* gpart = &g_part[b][s][0];
#pragma unroll
        for (int t = 0; t < 2; t++) {
            const int jcol = 16 * cAb + 8 * t + col2;
            *(float2*)&gpart[(16 * rA + g) * DDIM + jcol]     = make_float2(acc1[t][0], acc1[t][1]);
            *(float2*)&gpart[(16 * rA + g + 8) * DDIM + jcol] = make_float2(acc1[t][2], acc1[t][3]);
        }
        if (dual) {
#pragma unroll
            for (int t = 0; t < 2; t++) {
                const int jcol = 16 * cBb + 8 * t + col2;
                *(float2*)&gpart[(16 * rB + g) * DDIM + jcol]     = make_float2(acc2[t][0], acc2[t][1]);
                *(float2*)&gpart[(16 * rB + g + 8) * DDIM + jcol] = make_float2(acc2[t][2], acc2[t][3]);
            }
        }
    }

    // ---- column sums -> s_part ----
    {
        const int q = tid & 15, p = tid >> 4;
        sums[(q << 4) | p] = make_float4(sum0, sum1, sum2, sum3);
    }
    __syncthreads();
    if (tid < DDIM) {
        const int q = tid >> 2, r = tid & 3;
        const float* sp = (const float*)sums;
        float a = 0.f;
#pragma unroll
        for (int p = 0; p < 16; p++) a += sp[(((q << 4) | p) << 2) + r];
        s_part[b][s][tid] = a;
    }

    // ---- arrival protocol: last CTA of this batch finalizes ----
    __threadfence();
    __syncthreads();
    if (tid == 0) {
        unsigned int old = atomicAdd(&done_cnt[b], 1u);
        lastflag = (old == SSPLIT - 1);
        if (lastflag) done_cnt[b] = 0;   // reset for next graph replay
    }
    __syncthreads();
    if (!lastflag) return;
    __threadfence();   // acquire: make peers' partials visible

    // ================= inline finalize (smem reuse) =================
    float* cov  = (float*)dynsmem;               // 16 KB (reuse raw)
    float* ssum = (float*)&sums[0];              // 64 floats
    float* stdv = ssum + DDIM;                   // 64 floats

    for (int idx = tid; idx < DDIM * DDIM; idx += NTHREADS) {
        const int i = idx >> 6, j = idx & 63;
        const int src = ((i >> 4) <= (j >> 4)) ? idx : (j * DDIM + i);  // mirror lower
        float a = 0.f;
#pragma unroll
        for (int ss = 0; ss < SSPLIT; ss++) a += __ldcg(&g_part[b][ss][src]);
        cov[idx] = a;
    }
    if (tid < DDIM) {
        float a = 0.f;
#pragma unroll
        for (int ss = 0; ss < SSPLIT; ss++) a += __ldcg(&s_part[b][ss][tid]);
        ssum[tid] = a;
    }
    __syncthreads();

    const float invW  = 1.0f / (float)WTOT;
    const float invW1 = 1.0f / (float)(WTOT - 1);

    if (tid < DDIM) {
        float Si = ssum[tid];
        float cc = (cov[tid * DDIM + tid] - Si * Si * invW) * invW1;
        stdv[tid] = sqrtf(cc) + 1e-8f;
    }
    __syncthreads();

    if (tid < DDIM) {
        const int i = tid;
        float Si = ssum[i];
        float inv_si = 1.0f / stdv[i];
        float cnt = 0.f;
#pragma unroll 8
        for (int j = 0; j < DDIM; j++) {
            float cc = (cov[i * DDIM + j] - Si * ssum[j] * invW) * invW1;
            float corr = cc * inv_si / stdv[j];
            if (fabsf(corr) > 0.3f) cnt += 1.0f;
        }
        out[b * DDIM + i] = cnt - 1.0f;
    }
}

extern "C" void kernel_launch(void* const* d_in, const int* in_sizes, int n_in,
                              void* d_out, int out_size) {
    const float* x = (const float*)d_in[0];
    float* out = (float*)d_out;

    cudaFuncSetAttribute(gram_kernel, cudaFuncAttributeMaxDynamicSharedMemorySize, DYN_SMEM);

    dim3 grid(SSPLIT, BATCH);
    gram_kernel<<<grid, NTHREADS, DYN_SMEM>>>(x, out);
}

// round 11
// speedup vs baseline: 1.9545x; 1.9545x over previous
#include <cuda_runtime.h>
#include <cuda_bf16.h>
#include <cstdint>

#define BATCH    128
#define WTOT     8192
#define DDIM     64
#define SSPLIT   4
#define WSEG     (WTOT / SSPLIT)     // 2048
#define WC       128                 // w per staged tile
#define NTILES   (WSEG / WC)         // 16
#define NTHREADS 512
#define KSTEPS   8                   // 128 w / k16 per mma

// Scratch partials (no allocations allowed)
__device__ float g_part[BATCH][SSPLIT][DDIM * DDIM];   // upper 16x16 blocks only
__device__ float s_part[BATCH][SSPLIT][DDIM];
__device__ unsigned int done_cnt[BATCH];               // zero-init; reset by finalizer

__device__ __forceinline__ uint32_t smem_u32(const void* p) {
    uint32_t a;
    asm("{ .reg .u64 t; cvta.to.shared.u64 t, %1; cvt.u32.u64 %0, t; }" : "=r"(a) : "l"(p));
    return a;
}
__device__ __forceinline__ uint32_t cvt2(float hi, float lo) {
    uint32_t r; asm("cvt.rn.bf16x2.f32 %0, %1, %2;" : "=r"(r) : "f"(hi), "f"(lo)); return r;
}
__device__ __forceinline__ void sts64(uint32_t addr, uint32_t r0, uint32_t r1) {
    asm volatile("st.shared.v2.b32 [%0], {%1, %2};" :: "r"(addr), "r"(r0), "r"(r1) : "memory");
}
__device__ __forceinline__ void ldsm4t(uint32_t& r0, uint32_t& r1, uint32_t& r2, uint32_t& r3,
                                       uint32_t addr) {
    asm volatile("ldmatrix.sync.aligned.m8n8.x4.trans.shared.b16 {%0,%1,%2,%3}, [%4];"
                 : "=r"(r0), "=r"(r1), "=r"(r2), "=r"(r3) : "r"(addr));
}
__device__ __forceinline__ void mma16816(float* d,
                                         uint32_t a0, uint32_t a1, uint32_t a2, uint32_t a3,
                                         uint32_t b0, uint32_t b1) {
    asm volatile(
        "mma.sync.aligned.m16n8k16.row.col.f32.bf16.bf16.f32 "
        "{%0,%1,%2,%3}, {%4,%5,%6,%7}, {%8,%9}, {%0,%1,%2,%3};"
        : "+f"(d[0]), "+f"(d[1]), "+f"(d[2]), "+f"(d[3])
        : "r"(a0), "r"(a1), "r"(a2), "r"(a3), "r"(b0), "r"(b1));
}

// bf16 mma tile: [w][d], 128 B per row, XOR-swizzled by ((w&7)<<4).
#define SWZ(w, d2bytes) ((uint32_t)((w) * 128 + (d2bytes)) ^ (((uint32_t)(w) & 7u) << 4))

__global__ __launch_bounds__(NTHREADS, 2)
void gram_kernel(const float* __restrict__ x, float* __restrict__ out) {
    __shared__ __align__(16) uint8_t stage[2][WC * 128];   // 32 KB double-buffered
    __shared__ float4 sums[NTHREADS];                       // 8 KB
    __shared__ unsigned int lastflag;

    const int tid  = threadIdx.x;
    const int wid  = tid >> 5;
    const int lane = tid & 31;
    const int s = blockIdx.x;
    const int b = blockIdx.y;

    const uint32_t stg = smem_u32(&stage[0][0]);

    // Phase A role: chunk f = tid + 512*i -> w = f>>4 (w0 + 32*i), d-quad = tid&15
    const int d0 = 4 * (tid & 15);
    const int w0 = tid >> 4;                 // 0..31

    // ---- warp -> ONE upper-triangular 16x16 block ----
    int rA, cAb;
    if (wid < 4)      { rA = wid; cAb = wid;     }
    else if (wid < 7) { rA = 0;   cAb = wid - 3; }
    else if (wid < 9) { rA = 1;   cAb = wid - 5; }
    else              { rA = 2;   cAb = 3;       }
    const bool active = (wid < 10);

    const int kA = (lane & 7) + ((lane & 16) >> 1);
    const int kB = (lane & 7) + (lane & 8);
    const uint32_t swx = ((uint32_t)lane & 7u) << 4;
    const uint32_t oA1 = (uint32_t)(kA * 128 + (16 * rA + (lane & 8)) * 2) ^ swx;
    const uint32_t oB1 = (uint32_t)(kB * 128 + (16 * cAb + ((lane & 16) >> 1)) * 2) ^ swx;

    const float4* gp = (const float4*)(x + ((long)b * WTOT + (long)s * WSEG) * DDIM);

    float acc[2][4];
#pragma unroll
    for (int t = 0; t < 2; t++)
#pragma unroll
        for (int r = 0; r < 4; r++) acc[t][r] = 0.f;

    float sum0 = 0.f, sum1 = 0.f, sum2 = 0.f, sum3 = 0.f;

    float4 v[4];
#pragma unroll
    for (int i = 0; i < 4; i++) v[i] = gp[tid + 512 * i];

#pragma unroll 1
    for (int c = 0; c < NTILES; c++) {
        const uint32_t sbase = stg + (uint32_t)((c & 1) * (WC * 128));

        // ---- Phase A: cvt fp32->bf16, swizzled stage, column sums ----
#pragma unroll
        for (int i = 0; i < 4; i++) {
            uint32_t r0 = cvt2(v[i].y, v[i].x);
            uint32_t r1 = cvt2(v[i].w, v[i].z);
            sum0 += v[i].x; sum1 += v[i].y; sum2 += v[i].z; sum3 += v[i].w;
            const int w = w0 + 32 * i;
            sts64(sbase + SWZ(w, d0 * 2), r0, r1);
        }
        __syncthreads();

        // prefetch next tile (overlaps MMA)
        if (c + 1 < NTILES) {
#pragma unroll
            for (int i = 0; i < 4; i++) v[i] = gp[(c + 1) * 2048 + tid + 512 * i];
        }

        // ---- MMA: one upper-tri block per warp ----
        if (active) {
#pragma unroll
            for (int ks = 0; ks < KSTEPS; ks++) {
                const uint32_t kb = sbase + (uint32_t)(ks * 2048);
                uint32_t a0, a1, a2, a3, b0, b1, b2, b3;
                ldsm4t(a0, a1, a2, a3, kb + oA1);
                ldsm4t(b0, b1, b2, b3, kb + oB1);
                mma16816(acc[0], a0, a1, a2, a3, b0, b1);
                mma16816(acc[1], a0, a1, a2, a3, b2, b3);
            }
        }
        // MMA(c) ordered before phaseA(c+2) overwrite by sync(c+1).
    }

    // ---- write Gram partial block (upper triangle only) ----
    if (active) {
        const int g = lane >> 2;
        const int col2 = 2 * (lane & 3);
        float* gpart = &g_part[b][s][0];
#pragma unroll
        for (int t = 0; t < 2; t++) {
            const int jcol = 16 * cAb + 8 * t + col2;
            *(float2*)&gpart[(16 * rA + g) * DDIM + jcol]     = make_float2(acc[t][0], acc[t][1]);
            *(float2*)&gpart[(16 * rA + g + 8) * DDIM + jcol] = make_float2(acc[t][2], acc[t][3]);
        }
    }

    // ---- column sums -> s_part ----
    {
        const int q = tid & 15, p = tid >> 4;      // q: feature quad, p: 0..31
        sums[(q << 5) | p] = make_float4(sum0, sum1, sum2, sum3);
    }
    __syncthreads();
    if (tid < DDIM) {
        const int q = tid >> 2, r = tid & 3;
        const float* sp = (const float*)sums;
        float a = 0.f;
#pragma unroll
        for (int p = 0; p < 32; p++) a += sp[(((q << 5) | p) << 2) + r];
        s_part[b][s][tid] = a;
    }

    // ---- arrival protocol: last CTA of this batch finalizes ----
    __threadfence();
    __syncthreads();
    if (tid == 0) {
        unsigned int old = atomicAdd(&done_cnt[b], 1u);
        lastflag = (old == SSPLIT - 1);
        if (lastflag) done_cnt[b] = 0;   // reset for next graph replay
    }
    __syncthreads();
    if (!lastflag) return;
    __threadfence();   // acquire: make peers' partials visible

    // ================= inline finalize (smem reuse) =================
    float* cov  = (float*)&stage[0][0];          // 16 KB
    float* ssum = (float*)&sums[0];              // 64 floats
    float* stdv = ssum + DDIM;                   // 64 floats

    for (int idx = tid; idx < DDIM * DDIM; idx += NTHREADS) {
        const int i = idx >> 6, j = idx & 63;
        const int src = ((i >> 4) <= (j >> 4)) ? idx : (j * DDIM + i);  // mirror lower
        float a = 0.f;
#pragma unroll
        for (int ss = 0; ss < SSPLIT; ss++) a += __ldcg(&g_part[b][ss][src]);
        cov[idx] = a;
    }
    __syncthreads();   // sums smem is being repurposed below
    if (tid < DDIM) {
        float a = 0.f;
#pragma unroll
        for (int ss = 0; ss < SSPLIT; ss++) a += __ldcg(&s_part[b][ss][tid]);
        ssum[tid] = a;
    }
    __syncthreads();

    const float invW  = 1.0f / (float)WTOT;
    const float invW1 = 1.0f / (float)(WTOT - 1);

    if (tid < DDIM) {
        float Si = ssum[tid];
        float cc = (cov[tid * DDIM + tid] - Si * Si * invW) * invW1;
        stdv[tid] = sqrtf(cc) + 1e-8f;
    }
    __syncthreads();

    if (tid < DDIM) {
        const int i = tid;
        float Si = ssum[i];
        float inv_si = 1.0f / stdv[i];
        float cnt = 0.f;
#pragma unroll 8
        for (int j = 0; j < DDIM; j++) {
            float cc = (cov[i * DDIM + j] - Si * ssum[j] * invW) * invW1;
            float corr = cc * inv_si / stdv[j];
            if (fabsf(corr) > 0.3f) cnt += 1.0f;
        }
        out[b * DDIM + i] = cnt - 1.0f;
    }
}

extern "C" void kernel_launch(void* const* d_in, const int* in_sizes, int n_in,
                              void* d_out, int out_size) {
    const float* x = (const float*)d_in[0];
    float* out = (float*)d_out;

    dim3 grid(SSPLIT, BATCH);
    gram_kernel<<<grid, NTHREADS>>>(x, out);
}